// round 8
// baseline (speedup 1.0000x reference)
#include <cuda_runtime.h>
#include <math.h>

// out[b,c,h,w] = prod_{p=1..24} cos(x_p + w_p), 5x5 'same' window.
// cos(x+w_p) = cos(w_p) * (cos x - tan(w_p) sin x)
// => out = scale * prod_{p>=1} fmaf(-tan w_p, sin x, cos x), scale = prod cos w_p.
// Sliding window: thread owns column j + an 8-row segment, walks 12 tile rows;
// per row computes the 5 weight-row variants H_di, multiplying each into the
// pending output i = r - di; one output retires per row (di==4).
// Weights in __constant__ -> LDCU/UR operands (no GPR tax).
// 256 threads/block, 1024 blocks -> 8192 warps for latency hiding.

#define HW    64
#define PLANE (HW * HW)
#define TW    68   // 64 + 2*2 col halo
#define TR    36   // 32 output rows + 2*2 row halo

__device__   float g_stage[26];   // [p]= -tan(w_p) (p=1..24), [25]= prod cos
__constant__ float c_w[26];

__global__ void prep_kernel(const float* __restrict__ w)
{
    __shared__ float cwsh[25];
    const int p = threadIdx.x;
    if (p < 25) {
        float s, c;
        sincosf(w[p], &s, &c);      // accurate; only 25 values
        g_stage[p] = -s / c;
        cwsh[p] = c;
    }
    __syncwarp();
    if (p == 0) {
        float sc = 1.0f;
#pragma unroll
        for (int q = 1; q < 25; ++q) sc *= cwsh[q];
        g_stage[25] = sc;
    }
}

__global__ __launch_bounds__(256, 6)
void quanv_kernel(const float* __restrict__ x,
                  float* __restrict__ out)
{
    __shared__ float2 scs[TR][TW];   // (cos x, sin x); padded cells -> (1,0)

    const int blk   = blockIdx.x;
    const int plane = blk >> 1;
    const int base  = (blk & 1) * 32;          // first output row of this half
    const float* xp = x + (size_t)plane * PLANE;
    float* op = out + (size_t)plane * PLANE;
    const int tid = threadIdx.x;

    // Build 36x68 halo tile: tile row 0 = global row base-2, col 0 = global -2.
    for (int idx = tid; idx < TR * TW; idx += 256) {
        const int i  = idx / TW;
        const int j  = idx - i * TW;
        const int gi = base + i - 2;
        const int gj = j - 2;
        float v = 0.0f;
        if ((unsigned)gi < (unsigned)HW && (unsigned)gj < (unsigned)HW)
            v = xp[gi * HW + gj];
        float s, c;
        __sincosf(v, &s, &c);
        scs[i][j] = make_float2(c, s);
    }
    __syncthreads();

    const float scale = c_w[25];

    // Thread = (column j, segment of 8 output rows). Walk 12 tile rows;
    // at walk index r, variant di feeds pending output i = r - di.
    const int j  = tid & 63;          // 0..63
    const int i0 = (tid >> 6) * 8;    // 0, 8, 16, 24 (relative to base)

    float acc[8];

#pragma unroll
    for (int r = 0; r < 12; ++r) {
        const int tr = i0 + r;
        const float2 v0 = scs[tr][j + 0];
        const float2 v1 = scs[tr][j + 1];
        const float2 v2 = scs[tr][j + 2];
        const float2 v3 = scs[tr][j + 3];
        const float2 v4 = scs[tr][j + 4];

#pragma unroll
        for (int di = 0; di < 5; ++di) {
            const int i = r - di;                  // output index in segment
            if (i < 0 || i >= 8) continue;
            float h;
            if (di == 0) {
                // p = 0 (Z_0 wire) excluded: dj = 1..4 only.
                h = (fmaf(c_w[1], v1.y, v1.x) * fmaf(c_w[2], v2.y, v2.x))
                  * (fmaf(c_w[3], v3.y, v3.x) * fmaf(c_w[4], v4.y, v4.x));
            } else {
                const int b = di * 5;
                h = (fmaf(c_w[b    ], v0.y, v0.x) * fmaf(c_w[b + 1], v1.y, v1.x))
                  * (fmaf(c_w[b + 2], v2.y, v2.x) * fmaf(c_w[b + 3], v3.y, v3.x));
                h *= fmaf(c_w[b + 4], v4.y, v4.x);
            }
            acc[i] = (di == 0) ? h : acc[i] * h;
            if (di == 4)   // output complete -> store, free the register
                op[(base + i0 + i) * HW + j] = acc[i] * scale;
        }
    }
}

extern "C" void kernel_launch(void* const* d_in, const int* in_sizes, int n_in,
                              void* d_out, int out_size)
{
    const float* x = (const float*)d_in[0];
    const float* w = (const float*)d_in[1];
    float* out = (float*)d_out;

    const int planes = in_sizes[0] / PLANE;   // B*C = 512

    prep_kernel<<<1, 32>>>(w);

    // Stage -> __constant__ (D2D memcpy node; graph-capturable).
    void* stage_ptr = nullptr;
    cudaGetSymbolAddress(&stage_ptr, g_stage);
    cudaMemcpyToSymbolAsync(c_w, stage_ptr, 26 * sizeof(float), 0,
                            cudaMemcpyDeviceToDevice, 0);

    quanv_kernel<<<planes * 2, 256>>>(x, out);
}

// round 10
// speedup vs baseline: 1.1669x; 1.1669x over previous
#include <cuda_runtime.h>
#include <math.h>

// out[b,c,h,w] = prod_{p=1..24} cos(x_p + w_p), 5x5 'same' window.
// cos(x+w_p) = cos(w_p) * (cos x - tan(w_p) sin x)
// => out = scale * prod_{p>=1} fmaf(-tan w_p, sin x, cos x), scale = prod cos w_p.
// Block = one full 64x64 plane (grid 512, single wave at 4 blocks/SM).
// Halo cells are ALWAYS out-of-plane -> constant (cos,sin)=(1,0): no loads.
// (halo count = 68*68 - 64*64 = 528 = 272 top/bottom + 256 sides)
// Interior loaded as 4 float4 per thread (back-to-back LDGs, MLP=4).
// Main: thread owns column j + 16-row segment, walks 20 tile rows; per row
// computes 5 weight-row variants H_di, multiplies into pending output i=r-di.
// Weights in __constant__ -> uniform-register FFMA operands (no GPR tax).

#define HW    64
#define PLANE (HW * HW)
#define TW    68   // 64 + 2*2 col halo
#define TR    68   // 64 + 2*2 row halo

__device__   float g_stage[26];   // [p]= -tan(w_p) (p=1..24), [25]= prod cos
__constant__ float c_w[26];

__global__ void prep_kernel(const float* __restrict__ w)
{
    __shared__ float cwsh[25];
    const int p = threadIdx.x;
    if (p < 25) {
        float s, c;
        sincosf(w[p], &s, &c);      // accurate; only 25 values
        g_stage[p] = -s / c;
        cwsh[p] = c;
    }
    __syncwarp();
    if (p == 0) {
        float sc = 1.0f;
#pragma unroll
        for (int q = 1; q < 25; ++q) sc *= cwsh[q];
        g_stage[25] = sc;
    }
}

__global__ __launch_bounds__(256, 4)
void quanv_kernel(const float* __restrict__ x,
                  float* __restrict__ out)
{
    __shared__ float2 scs[TR][TW];   // (cos x, sin x); halo -> (1,0)

    const int plane = blockIdx.x;
    const float* xp = x + (size_t)plane * PLANE;
    float* op = out + (size_t)plane * PLANE;
    const int tid = threadIdx.x;

    // ---- Halo fill: rows 0,1,66,67 (4*68 = 272 cells) + cols 0,1,66,67 of
    // rows 2..65 (64*4 = 256 cells) = 528 cells, all constant (1,0).
    for (int h = tid; h < 528; h += 256) {
        int r, c;
        if (h < 272) {                 // top/bottom full rows
            int rr = h / TW;           // 0..3
            c = h - rr * TW;
            r = (rr < 2) ? rr : (64 + rr);   // 0,1,66,67
        } else {                       // side columns, interior rows
            int q = h - 272;           // 0..255
            r = 2 + (q >> 2);          // 2..65
            int cc = q & 3;            // 0..3
            c = (cc < 2) ? cc : (64 + cc);   // 0,1,66,67
        }
        scs[r][c] = make_float2(1.0f, 0.0f);
    }

    // ---- Interior: 64 rows x 16 float4 = 1024 vector loads, 4 per thread,
    // issued back-to-back for MLP, then sincos + store.
    float4 xv[4];
#pragma unroll
    for (int k = 0; k < 4; ++k) {
        const int q = tid + 256 * k;       // 0..1023
        xv[k] = *reinterpret_cast<const float4*>(xp + (q >> 4) * HW + ((q & 15) << 2));
    }
#pragma unroll
    for (int k = 0; k < 4; ++k) {
        const int q   = tid + 256 * k;
        const int row = (q >> 4) + 2;      // tile row 2..65
        const int col = ((q & 15) << 2) + 2;
        float s, c;
        __sincosf(xv[k].x, &s, &c); scs[row][col + 0] = make_float2(c, s);
        __sincosf(xv[k].y, &s, &c); scs[row][col + 1] = make_float2(c, s);
        __sincosf(xv[k].z, &s, &c); scs[row][col + 2] = make_float2(c, s);
        __sincosf(xv[k].w, &s, &c); scs[row][col + 3] = make_float2(c, s);
    }
    __syncthreads();

    const float scale = c_w[25];

    // ---- Main: thread = (column j, 16-row segment). Walk 20 tile rows;
    // at walk index r, variant di feeds pending output i = r - di.
    const int j  = tid & 63;          // 0..63
    const int i0 = (tid >> 6) * 16;   // 0,16,32,48

    float acc[16];

#pragma unroll
    for (int r = 0; r < 20; ++r) {
        const int tr = i0 + r;
        const float2 v0 = scs[tr][j + 0];
        const float2 v1 = scs[tr][j + 1];
        const float2 v2 = scs[tr][j + 2];
        const float2 v3 = scs[tr][j + 3];
        const float2 v4 = scs[tr][j + 4];

#pragma unroll
        for (int di = 0; di < 5; ++di) {
            const int i = r - di;                  // output index in segment
            if (i < 0 || i >= 16) continue;
            float h;
            if (di == 0) {
                // p = 0 (Z_0 wire) excluded: dj = 1..4 only.
                h = (fmaf(c_w[1], v1.y, v1.x) * fmaf(c_w[2], v2.y, v2.x))
                  * (fmaf(c_w[3], v3.y, v3.x) * fmaf(c_w[4], v4.y, v4.x));
            } else {
                const int b = di * 5;
                h = (fmaf(c_w[b    ], v0.y, v0.x) * fmaf(c_w[b + 1], v1.y, v1.x))
                  * (fmaf(c_w[b + 2], v2.y, v2.x) * fmaf(c_w[b + 3], v3.y, v3.x));
                h *= fmaf(c_w[b + 4], v4.y, v4.x);
            }
            acc[i] = (di == 0) ? h : acc[i] * h;
            if (di == 4)   // output complete -> store, free the register
                op[(i0 + i) * HW + j] = acc[i] * scale;
        }
    }
}

extern "C" void kernel_launch(void* const* d_in, const int* in_sizes, int n_in,
                              void* d_out, int out_size)
{
    const float* x = (const float*)d_in[0];
    const float* w = (const float*)d_in[1];
    float* out = (float*)d_out;

    const int planes = in_sizes[0] / PLANE;   // B*C = 512

    prep_kernel<<<1, 32>>>(w);

    // Stage -> __constant__ (D2D memcpy node; graph-capturable).
    void* stage_ptr = nullptr;
    cudaGetSymbolAddress(&stage_ptr, g_stage);
    cudaMemcpyToSymbolAsync(c_w, stage_ptr, 26 * sizeof(float), 0,
                            cudaMemcpyDeviceToDevice, 0);

    quanv_kernel<<<planes, 256>>>(x, out);
}

// round 12
// speedup vs baseline: 1.7519x; 1.5013x over previous
#include <cuda_runtime.h>
#include <math.h>

// out[b,c,h,w] = prod_{p=1..24} cos(x_p + w_p), 5x5 'same' window.
// cos(x+w_p) = cos(w_p) * (cos x - tan(w_p) sin x)
// => out = scale * prod_{p>=1} fmaf(-tan w_p, sin x, cos x), scale = prod cos w_p.
// Block = one full 64x64 plane (grid 512, single wave at ~3.5 blocks/SM).
// Halo cells are ALWAYS out-of-plane -> constant (cos,sin)=(1,0): no loads.
// Interior loaded as 4 float4 per thread (back-to-back LDGs, MLP=4).
// Main: thread owns column j + 16-row segment, walks 20 tile rows; per row
// computes 5 weight-row variants H_di, multiplies into pending output i=r-di.
// Weights in __constant__ -> uniform-register FFMA operands (no GPR tax).
// prep writes DIRECTLY into the constant backing store (symbol address passed
// from host) -> 2-node graph, no memcpy node. Safe: const caches are cold at
// each launch boundary on sm_103a, and prep completes before quanv launches.

#define HW    64
#define PLANE (HW * HW)
#define TW    68   // 64 + 2*2 col halo
#define TR    68   // 64 + 2*2 row halo

__constant__ float c_w[26];   // [p]= -tan(w_p) (p=1..24), [25]= prod cos

__global__ void prep_kernel(const float* __restrict__ w, float* __restrict__ cw_store)
{
    __shared__ float cwsh[25];
    const int p = threadIdx.x;
    if (p < 25) {
        float s, c;
        sincosf(w[p], &s, &c);      // accurate; only 25 values
        cw_store[p] = -s / c;
        cwsh[p] = c;
    }
    __syncwarp();
    if (p == 0) {
        float sc = 1.0f;
#pragma unroll
        for (int q = 1; q < 25; ++q) sc *= cwsh[q];
        cw_store[25] = sc;
    }
}

__global__ __launch_bounds__(256, 4)
void quanv_kernel(const float* __restrict__ x,
                  float* __restrict__ out)
{
    __shared__ float2 scs[TR][TW];   // (cos x, sin x); halo -> (1,0)

    const int plane = blockIdx.x;
    const float* xp = x + (size_t)plane * PLANE;
    float* op = out + (size_t)plane * PLANE;
    const int tid = threadIdx.x;

    // ---- Halo fill: rows 0,1,66,67 (4*68 = 272 cells) + cols 0,1,66,67 of
    // rows 2..65 (64*4 = 256 cells) = 528 cells, all constant (1,0).
    for (int h = tid; h < 528; h += 256) {
        int r, c;
        if (h < 272) {                 // top/bottom full rows
            int rr = h / TW;           // 0..3
            c = h - rr * TW;
            r = (rr < 2) ? rr : (64 + rr);   // 0,1,66,67
        } else {                       // side columns, interior rows
            int q = h - 272;           // 0..255
            r = 2 + (q >> 2);          // 2..65
            int cc = q & 3;            // 0..3
            c = (cc < 2) ? cc : (64 + cc);   // 0,1,66,67
        }
        scs[r][c] = make_float2(1.0f, 0.0f);
    }

    // ---- Interior: 64 rows x 16 float4 = 1024 vector loads, 4 per thread,
    // issued back-to-back for MLP, then sincos + store.
    float4 xv[4];
#pragma unroll
    for (int k = 0; k < 4; ++k) {
        const int q = tid + 256 * k;       // 0..1023
        xv[k] = *reinterpret_cast<const float4*>(xp + (q >> 4) * HW + ((q & 15) << 2));
    }
#pragma unroll
    for (int k = 0; k < 4; ++k) {
        const int q   = tid + 256 * k;
        const int row = (q >> 4) + 2;      // tile row 2..65
        const int col = ((q & 15) << 2) + 2;
        float s, c;
        __sincosf(xv[k].x, &s, &c); scs[row][col + 0] = make_float2(c, s);
        __sincosf(xv[k].y, &s, &c); scs[row][col + 1] = make_float2(c, s);
        __sincosf(xv[k].z, &s, &c); scs[row][col + 2] = make_float2(c, s);
        __sincosf(xv[k].w, &s, &c); scs[row][col + 3] = make_float2(c, s);
    }
    __syncthreads();

    const float scale = c_w[25];

    // ---- Main: thread = (column j, 16-row segment). Walk 20 tile rows;
    // at walk index r, variant di feeds pending output i = r - di.
    const int j  = tid & 63;          // 0..63
    const int i0 = (tid >> 6) * 16;   // 0,16,32,48

    float acc[16];

#pragma unroll
    for (int r = 0; r < 20; ++r) {
        const int tr = i0 + r;
        const float2 v0 = scs[tr][j + 0];
        const float2 v1 = scs[tr][j + 1];
        const float2 v2 = scs[tr][j + 2];
        const float2 v3 = scs[tr][j + 3];
        const float2 v4 = scs[tr][j + 4];

#pragma unroll
        for (int di = 0; di < 5; ++di) {
            const int i = r - di;                  // output index in segment
            if (i < 0 || i >= 16) continue;
            float h;
            if (di == 0) {
                // p = 0 (Z_0 wire) excluded: dj = 1..4 only.
                h = (fmaf(c_w[1], v1.y, v1.x) * fmaf(c_w[2], v2.y, v2.x))
                  * (fmaf(c_w[3], v3.y, v3.x) * fmaf(c_w[4], v4.y, v4.x));
            } else {
                const int b = di * 5;
                h = (fmaf(c_w[b    ], v0.y, v0.x) * fmaf(c_w[b + 1], v1.y, v1.x))
                  * (fmaf(c_w[b + 2], v2.y, v2.x) * fmaf(c_w[b + 3], v3.y, v3.x));
                h *= fmaf(c_w[b + 4], v4.y, v4.x);
            }
            acc[i] = (di == 0) ? h : acc[i] * h;
            if (di == 4)   // output complete -> store, free the register
                op[(i0 + i) * HW + j] = acc[i] * scale;
        }
    }
}

extern "C" void kernel_launch(void* const* d_in, const int* in_sizes, int n_in,
                              void* d_out, int out_size)
{
    const float* x = (const float*)d_in[0];
    const float* w = (const float*)d_in[1];
    float* out = (float*)d_out;

    const int planes = in_sizes[0] / PLANE;   // B*C = 512

    // Device pointer to the __constant__ backing store (no allocation).
    void* cw_ptr = nullptr;
    cudaGetSymbolAddress(&cw_ptr, c_w);

    prep_kernel<<<1, 32>>>(w, (float*)cw_ptr);
    quanv_kernel<<<planes, 256>>>(x, out);
}

// round 13
// speedup vs baseline: 2.0804x; 1.1875x over previous
#include <cuda_runtime.h>
#include <math.h>

// out[b,c,h,w] = prod_{p=1..24} cos(x_p + w_p), 5x5 'same' window.
// cos(x+w_p) = cos(w_p) * (cos x - tan(w_p) sin x)
// => out = scale * prod_{p>=1} fmaf(-tan w_p, sin x, cos x), scale = prod cos w_p.
// Block = HALF plane (32 rows x 64 cols), 128 threads, grid 1024:
// 1024/148 = 6.92 avg vs 7 max resident -> ~1% wave tail (vs 16% at grid 512).
// Out-of-plane halo cells are constant (cos,sin)=(1,0): no loads.
// Real rows loaded as back-to-back float4 (MLP>=4), sincos to smem.
// Main: thread owns column j + 16-row segment, walks 20 tile rows; per row
// computes 5 weight-row variants H_di, multiplies into pending output i=r-di.
// Weights in __constant__ -> uniform-register FFMA operands (no GPR tax);
// prep writes directly into the constant backing store (2-node graph).

#define HW    64
#define PLANE (HW * HW)
#define TW    68   // 64 + 2*2 col halo
#define TR    36   // 32 + 2*2 row halo

__constant__ float c_w[26];   // [p]= -tan(w_p) (p=1..24), [25]= prod cos

__global__ void prep_kernel(const float* __restrict__ w, float* __restrict__ cw_store)
{
    __shared__ float cwsh[25];
    const int p = threadIdx.x;
    if (p < 25) {
        float s, c;
        sincosf(w[p], &s, &c);      // accurate; only 25 values
        cw_store[p] = -s / c;
        cwsh[p] = c;
    }
    __syncwarp();
    if (p == 0) {
        float sc = 1.0f;
#pragma unroll
        for (int q = 1; q < 25; ++q) sc *= cwsh[q];
        cw_store[25] = sc;
    }
}

__global__ __launch_bounds__(128, 8)
void quanv_kernel(const float* __restrict__ x,
                  float* __restrict__ out)
{
    __shared__ float2 scs[TR][TW];   // (cos x, sin x); halo -> (1,0)

    const int blk   = blockIdx.x;
    const int plane = blk >> 1;
    const int hb    = blk & 1;            // 0 = top half, 1 = bottom half
    const int base  = hb * 32;            // first output row
    const float* xp = x + (size_t)plane * PLANE;
    float* op = out + (size_t)plane * PLANE;
    const int tid = threadIdx.x;

    // ---- Constant halo fill (272 cells):
    // 2 out-of-plane edge rows (full 68 cols) + 4 halo cols over the 34 real rows.
    const int e0 = hb ? 34 : 0;   // edge tile rows e0, e0+1
    const int s0 = hb ? 0 : 2;    // first real tile row (34 of them)
    for (int h = tid; h < 272; h += 128) {
        int r, c;
        if (h < 136) {                    // 2 edge rows x 68
            r = e0 + (h / TW);
            c = h - (h / TW) * TW;
        } else {                          // 34 rows x cols {0,1,66,67}
            int q = h - 136;              // 0..135
            r = s0 + (q >> 2);
            int cc = q & 3;
            c = (cc < 2) ? cc : (64 + cc);
        }
        scs[r][c] = make_float2(1.0f, 0.0f);
    }

    // ---- Interior: 34 real rows (global band gb..gb+33) x 16 float4 = 544.
    // 4 full passes + 1 predicated, all LDGs issued back-to-back (MLP).
    const int gb = hb ? 30 : 0;           // first global row of the band
    const int t0 = s0;                    // tile row of band row 0
    float4 xv[5];
#pragma unroll
    for (int k = 0; k < 4; ++k) {
        const int q = tid + 128 * k;      // 0..511
        xv[k] = *reinterpret_cast<const float4*>(xp + (gb + (q >> 4)) * HW + ((q & 15) << 2));
    }
    if (tid < 32) {                       // band rows 32,33
        const int q = 512 + tid;
        xv[4] = *reinterpret_cast<const float4*>(xp + (gb + (q >> 4)) * HW + ((q & 15) << 2));
    }
#pragma unroll
    for (int k = 0; k < 5; ++k) {
        const int q = tid + 128 * k;
        if (k == 4 && tid >= 32) break;
        const int row = t0 + (q >> 4);    // tile row
        const int col = ((q & 15) << 2) + 2;
        float s, c;
        __sincosf(xv[k].x, &s, &c); scs[row][col + 0] = make_float2(c, s);
        __sincosf(xv[k].y, &s, &c); scs[row][col + 1] = make_float2(c, s);
        __sincosf(xv[k].z, &s, &c); scs[row][col + 2] = make_float2(c, s);
        __sincosf(xv[k].w, &s, &c); scs[row][col + 3] = make_float2(c, s);
    }
    __syncthreads();

    const float scale = c_w[25];

    // ---- Main: thread = (column j, 16-row segment). Walk 20 tile rows;
    // at walk index r, variant di feeds pending output i = r - di.
    const int j  = tid & 63;          // 0..63
    const int i0 = (tid >> 6) * 16;   // 0 or 16 (relative to base)

    float acc[16];

#pragma unroll
    for (int r = 0; r < 20; ++r) {
        const int tr = i0 + r;
        const float2 v0 = scs[tr][j + 0];
        const float2 v1 = scs[tr][j + 1];
        const float2 v2 = scs[tr][j + 2];
        const float2 v3 = scs[tr][j + 3];
        const float2 v4 = scs[tr][j + 4];

#pragma unroll
        for (int di = 0; di < 5; ++di) {
            const int i = r - di;                  // output index in segment
            if (i < 0 || i >= 16) continue;
            float h;
            if (di == 0) {
                // p = 0 (Z_0 wire) excluded: dj = 1..4 only.
                h = (fmaf(c_w[1], v1.y, v1.x) * fmaf(c_w[2], v2.y, v2.x))
                  * (fmaf(c_w[3], v3.y, v3.x) * fmaf(c_w[4], v4.y, v4.x));
            } else {
                const int b = di * 5;
                h = (fmaf(c_w[b    ], v0.y, v0.x) * fmaf(c_w[b + 1], v1.y, v1.x))
                  * (fmaf(c_w[b + 2], v2.y, v2.x) * fmaf(c_w[b + 3], v3.y, v3.x));
                h *= fmaf(c_w[b + 4], v4.y, v4.x);
            }
            acc[i] = (di == 0) ? h : acc[i] * h;
            if (di == 4)   // output complete -> store, free the register
                op[(base + i0 + i) * HW + j] = acc[i] * scale;
        }
    }
}

extern "C" void kernel_launch(void* const* d_in, const int* in_sizes, int n_in,
                              void* d_out, int out_size)
{
    const float* x = (const float*)d_in[0];
    const float* w = (const float*)d_in[1];
    float* out = (float*)d_out;

    const int planes = in_sizes[0] / PLANE;   // B*C = 512

    // Device pointer to the __constant__ backing store (no allocation).
    void* cw_ptr = nullptr;
    cudaGetSymbolAddress(&cw_ptr, c_w);

    prep_kernel<<<1, 32>>>(w, (float*)cw_ptr);
    quanv_kernel<<<planes * 2, 128>>>(x, out);
}